// round 11
// baseline (speedup 1.0000x reference)
#include <cuda_runtime.h>
#include <cstdint>
#include <math.h>

#define HID 2048
#define NTOK 4096
#define HEADS 16
#define HDIM 128

// ---- scratch (static device arrays; no allocations allowed) ----
__device__ float g_Q[NTOK * HID];
__device__ float g_K[NTOK * HID];
__device__ float g_V[NTOK * HID];
__device__ float g_AO[NTOK * HID];
__device__ float g_Xr[NTOK * HID];        // tf32-rounded hidden_states
__device__ float g_Wr[4][HID * HID];      // tf32-rounded weights (same layout)

// =====================================================================
// helpers
// =====================================================================
__device__ __forceinline__ unsigned f2tf32(float f) {
    unsigned u;
    asm("cvt.rna.tf32.f32 %0, %1;" : "=r"(u) : "f"(f));
    return u;
}
__device__ __forceinline__ void mma_tf32(float* c, const unsigned* a,
                                         const unsigned* b) {
    asm volatile(
        "mma.sync.aligned.m16n8k8.row.col.f32.tf32.tf32.f32 "
        "{%0,%1,%2,%3}, {%4,%5,%6,%7}, {%8,%9}, {%0,%1,%2,%3};\n"
        : "+f"(c[0]), "+f"(c[1]), "+f"(c[2]), "+f"(c[3])
        : "r"(a[0]), "r"(a[1]), "r"(a[2]), "r"(a[3]),
          "r"(b[0]), "r"(b[1]));
}
__device__ __forceinline__ void cp16(void* smem_dst, const void* g) {
    unsigned saddr = (unsigned)__cvta_generic_to_shared(smem_dst);
    asm volatile("cp.async.cg.shared.global [%0], [%1], 16;\n"
                 :: "r"(saddr), "l"(g));
}
__device__ __forceinline__ void cp_commit() {
    asm volatile("cp.async.commit_group;\n");
}
__device__ __forceinline__ void cp_wait1() {
    asm volatile("cp.async.wait_group 1;\n");
}
__device__ __forceinline__ void cp_wait0() {
    asm volatile("cp.async.wait_group 0;\n");
}

// =====================================================================
// prep: round X and the 4 weights to exact tf32 values (rna), in gmem.
// =====================================================================
__global__ __launch_bounds__(256)
void round_prep(const float* __restrict__ X,
                const float* __restrict__ w0, const float* __restrict__ w1,
                const float* __restrict__ w2, const float* __restrict__ w3,
                float* __restrict__ Xr,
                float* __restrict__ r0, float* __restrict__ r1,
                float* __restrict__ r2, float* __restrict__ r3)
{
    int z = blockIdx.y;
    const float4* src;
    float4* dst;
    int n4;
    if (z == 0)      { src = (const float4*)X;  dst = (float4*)Xr; n4 = NTOK * HID / 4; }
    else if (z == 1) { src = (const float4*)w0; dst = (float4*)r0; n4 = HID * HID / 4; }
    else if (z == 2) { src = (const float4*)w1; dst = (float4*)r1; n4 = HID * HID / 4; }
    else if (z == 3) { src = (const float4*)w2; dst = (float4*)r2; n4 = HID * HID / 4; }
    else             { src = (const float4*)w3; dst = (float4*)r3; n4 = HID * HID / 4; }

    int i = blockIdx.x * blockDim.x + threadIdx.x;
    int stride = gridDim.x * blockDim.x;
    for (; i < n4; i += stride) {
        float4 v = src[i];
        v.x = __uint_as_float(f2tf32(v.x));
        v.y = __uint_as_float(f2tf32(v.y));
        v.z = __uint_as_float(f2tf32(v.z));
        v.w = __uint_as_float(f2tf32(v.w));
        dst[i] = v;
    }
}

// =====================================================================
// TF32 tensor-core GEMM with bias (pre-rounded inputs, no mainloop cvt)
// 128x128x32 block tile, 128 threads (4 warps, 2x2), warp tile 64x64.
// =====================================================================
#define ASTR 36
#define BSTR 136
#define GEMM_SMEM ((2 * 128 * ASTR + 2 * 32 * BSTR) * 4)   // 71680 B

__device__ __forceinline__
void gemm_body(const float* __restrict__ A, const float* __restrict__ B,
               const float* __restrict__ bias, float* __restrict__ C)
{
    extern __shared__ float gsm[];
    float* Asm[2] = { gsm, gsm + 128 * ASTR };
    float* Bsm[2] = { gsm + 2 * 128 * ASTR, gsm + 2 * 128 * ASTR + 32 * BSTR };

    const int tid  = threadIdx.x;
    const int lane = tid & 31;
    const int g    = lane >> 2;
    const int t    = lane & 3;
    const int wid  = tid >> 5;
    const int warpM = wid & 1;
    const int warpN = wid >> 1;
    const int row0 = blockIdx.y * 128;
    const int col0 = blockIdx.x * 128;

    float acc[4][8][4];
    #pragma unroll
    for (int i = 0; i < 4; i++)
        #pragma unroll
        for (int j = 0; j < 8; j++)
            #pragma unroll
            for (int c = 0; c < 4; c++) acc[i][j][c] = 0.f;

    const int nk = HID >> 5;

    #define LOAD_TILE(bufi, kt_) { \
        const float* ag = A + (size_t)row0 * HID + (kt_) * 32; \
        _Pragma("unroll") \
        for (int j = 0; j < 8; j++) { \
            int idx = j * 128 + tid; \
            int r = idx >> 3, c = (idx & 7) * 4; \
            cp16(&Asm[bufi][r * ASTR + c], ag + (size_t)r * HID + c); \
        } \
        const float* bg = B + (size_t)((kt_) * 32) * HID + col0; \
        _Pragma("unroll") \
        for (int j = 0; j < 8; j++) { \
            int idx = j * 128 + tid; \
            int kr = idx >> 5, n = (idx & 31) * 4; \
            cp16(&Bsm[bufi][kr * BSTR + n], bg + (size_t)kr * HID + n); \
        } \
        cp_commit(); }

    LOAD_TILE(0, 0);

    int buf = 0;
    for (int kt = 0; kt < nk; kt++) {
        if (kt + 1 < nk) {
            LOAD_TILE(buf ^ 1, kt + 1);
            cp_wait1();
        } else {
            cp_wait0();
        }
        __syncthreads();

        const unsigned* as = (const unsigned*)Asm[buf];
        const unsigned* bs = (const unsigned*)Bsm[buf];

        #pragma unroll
        for (int kk = 0; kk < 32; kk += 8) {
            unsigned bf[8][2];
            #pragma unroll
            for (int tn = 0; tn < 8; tn++) {
                int n = warpN * 64 + tn * 8 + g;
                bf[tn][0] = bs[(kk +     t) * BSTR + n];
                bf[tn][1] = bs[(kk + 4 + t) * BSTR + n];
            }
            unsigned af[4][4];
            #pragma unroll
            for (int tm = 0; tm < 4; tm++) {
                int m = warpM * 64 + tm * 16 + g;
                af[tm][0] = as[m * ASTR + kk + t];
                af[tm][1] = as[(m + 8) * ASTR + kk + t];
                af[tm][2] = as[m * ASTR + kk + 4 + t];
                af[tm][3] = as[(m + 8) * ASTR + kk + 4 + t];
            }
            #pragma unroll
            for (int tm = 0; tm < 4; tm++)
                #pragma unroll
                for (int tn = 0; tn < 8; tn++)
                    mma_tf32(acc[tm][tn], af[tm], bf[tn]);
        }
        __syncthreads();
        buf ^= 1;
    }
    #undef LOAD_TILE

    #pragma unroll
    for (int tm = 0; tm < 4; tm++) {
        int mrow = row0 + warpM * 64 + tm * 16 + g;
        #pragma unroll
        for (int tn = 0; tn < 8; tn++) {
            int ncol = col0 + warpN * 64 + tn * 8 + t * 2;
            float b0 = bias[ncol], b1 = bias[ncol + 1];
            float2 v0 = make_float2(acc[tm][tn][0] + b0, acc[tm][tn][1] + b1);
            float2 v1 = make_float2(acc[tm][tn][2] + b0, acc[tm][tn][3] + b1);
            *(float2*)(C + (size_t)mrow * HID + ncol) = v0;
            *(float2*)(C + (size_t)(mrow + 8) * HID + ncol) = v1;
        }
    }
}

__global__ __launch_bounds__(128)
void qkv_gemm(const float* __restrict__ A,
              const float* __restrict__ W0, const float* __restrict__ W1,
              const float* __restrict__ W2,
              const float* __restrict__ b0, const float* __restrict__ b1,
              const float* __restrict__ b2,
              float* __restrict__ C0, float* __restrict__ C1,
              float* __restrict__ C2)
{
    const float* W = (blockIdx.z == 0) ? W0 : (blockIdx.z == 1) ? W1 : W2;
    const float* b = (blockIdx.z == 0) ? b0 : (blockIdx.z == 1) ? b1 : b2;
    float*       C = (blockIdx.z == 0) ? C0 : (blockIdx.z == 1) ? C1 : C2;
    gemm_body(A, W, b, C);
}

__global__ __launch_bounds__(128)
void tf32_gemm_bias(const float* __restrict__ A, const float* __restrict__ B,
                    const float* __restrict__ bias, float* __restrict__ C)
{
    gemm_body(A, B, bias, C);
}

// =====================================================================
// Per-head LayerNorm over head_dim=128 for Q and K (in place).
// =====================================================================
__device__ __forceinline__ void ln_head(float* p, const float* g,
                                        const float* be, int lane)
{
    float4 x = *(float4*)(p + lane * 4);
    float s  = x.x + x.y + x.z + x.w;
    float ss = x.x * x.x + x.y * x.y + x.z * x.z + x.w * x.w;
    #pragma unroll
    for (int off = 16; off > 0; off >>= 1) {
        s  += __shfl_xor_sync(0xffffffffu, s,  off);
        ss += __shfl_xor_sync(0xffffffffu, ss, off);
    }
    float mean = s * (1.f / 128.f);
    float var  = ss * (1.f / 128.f) - mean * mean;
    float rstd = rsqrtf(var + 1e-6f);
    float4 gg = *(const float4*)(g  + lane * 4);
    float4 bb = *(const float4*)(be + lane * 4);
    x.x = (x.x - mean) * rstd * gg.x + bb.x;
    x.y = (x.y - mean) * rstd * gg.y + bb.y;
    x.z = (x.z - mean) * rstd * gg.z + bb.z;
    x.w = (x.w - mean) * rstd * gg.w + bb.w;
    *(float4*)(p + lane * 4) = x;
}

__global__ __launch_bounds__(512)
void qk_ln(float* __restrict__ Q, float* __restrict__ K,
           const float* __restrict__ qg, const float* __restrict__ qb,
           const float* __restrict__ kg, const float* __restrict__ kb)
{
    int tk = blockIdx.x;
    int h = threadIdx.x >> 5;
    int lane = threadIdx.x & 31;
    ln_head(Q + (size_t)tk * HID + h * HDIM, qg, qb, lane);
    ln_head(K + (size_t)tk * HID + h * HDIM, kg, kb, lane);
}

// =====================================================================
// Tensor-core flash attention (legacy tf32 mma).
// All smem operands (Q, K, V, P) stored PRE-ROUNDED to tf32 ->
// inner loops are bare LDS + MMA (no cvt). Bit-identical to R10:
// cvt.rna is idempotent, and l sums the unrounded p as before.
// =====================================================================
#define QSTR 132
#define KSTR 132
#define VSTR 136
#define PSTR 68
#define FLASH_SMEM ((128 * QSTR + 64 * KSTR + 64 * VSTR + 8 * 16 * PSTR) * 4)

__global__ __launch_bounds__(256)
void flash_attn_tc(const float* __restrict__ Qg, const float* __restrict__ Kg,
                   const float* __restrict__ Vg, float* __restrict__ Og)
{
    extern __shared__ float sm[];
    float* Qs = sm;
    float* Ks = Qs + 128 * QSTR;
    float* Vs = Ks + 64 * KSTR;
    float* Pw = Vs + 64 * VSTR;

    const int tid  = threadIdx.x;
    const int lane = tid & 31;
    const int w    = tid >> 5;
    const int g    = lane >> 2;
    const int t    = lane & 3;
    const int bh = blockIdx.y;
    const int b  = bh >> 4, h = bh & 15;
    const int q0 = blockIdx.x * 128;
    const size_t base = (size_t)b * 2048 * HID + (size_t)h * HDIM;
    const float scale = 0.08838834764831845f;

    float* Ps = Pw + w * 16 * PSTR;
    const int wrow = w * 16;

    // Q tile: scale then round to tf32 once (same bits MMA saw in R10)
    for (int i = tid; i < 128 * 32; i += 256) {
        int r = i >> 5, c4 = (i & 31) << 2;
        float4 q = *(const float4*)(Qg + base + (size_t)(q0 + r) * HID + c4);
        uint4 qu;
        qu.x = f2tf32(q.x * scale);
        qu.y = f2tf32(q.y * scale);
        qu.z = f2tf32(q.z * scale);
        qu.w = f2tf32(q.w * scale);
        *(uint4*)(Qs + r * QSTR + c4) = qu;
    }

    float m0 = -1e30f, m1 = -1e30f, l0 = 0.f, l1 = 0.f;
    float o[16][4];
    #pragma unroll
    for (int nt = 0; nt < 16; nt++)
        #pragma unroll
        for (int c = 0; c < 4; c++) o[nt][c] = 0.f;

    for (int kt = 0; kt < 2048 / 64; kt++) {
        const int k0 = kt * 64;
        __syncthreads();
        // K/V tiles: round to tf32 at store (8 warps reuse each element)
        for (int i = tid; i < 64 * 32; i += 256) {
            int r = i >> 5, c4 = (i & 31) << 2;
            float4 kv = *(const float4*)(Kg + base + (size_t)(k0 + r) * HID + c4);
            uint4 ku;
            ku.x = f2tf32(kv.x); ku.y = f2tf32(kv.y);
            ku.z = f2tf32(kv.z); ku.w = f2tf32(kv.w);
            *(uint4*)(Ks + r * KSTR + c4) = ku;
            float4 vv = *(const float4*)(Vg + base + (size_t)(k0 + r) * HID + c4);
            uint4 vu;
            vu.x = f2tf32(vv.x); vu.y = f2tf32(vv.y);
            vu.z = f2tf32(vv.z); vu.w = f2tf32(vv.w);
            *(uint4*)(Vs + r * VSTR + c4) = vu;
        }
        __syncthreads();

        const unsigned* Qu = (const unsigned*)Qs;
        const unsigned* Ku = (const unsigned*)Ks;
        const unsigned* Vu = (const unsigned*)Vs;
        const unsigned* Pu = (const unsigned*)Ps;

        float s[8][4];
        #pragma unroll
        for (int nt = 0; nt < 8; nt++)
            #pragma unroll
            for (int c = 0; c < 4; c++) s[nt][c] = 0.f;

        #pragma unroll
        for (int kk = 0; kk < 128; kk += 8) {
            unsigned af[4];
            af[0] = Qu[(wrow + g) * QSTR + kk + t];
            af[1] = Qu[(wrow + 8 + g) * QSTR + kk + t];
            af[2] = Qu[(wrow + g) * QSTR + kk + 4 + t];
            af[3] = Qu[(wrow + 8 + g) * QSTR + kk + 4 + t];
            #pragma unroll
            for (int nt = 0; nt < 8; nt++) {
                unsigned bf[2];
                bf[0] = Ku[(nt * 8 + g) * KSTR + kk + t];
                bf[1] = Ku[(nt * 8 + g) * KSTR + kk + 4 + t];
                mma_tf32(s[nt], af, bf);
            }
        }

        float mx0 = -1e30f, mx1 = -1e30f;
        #pragma unroll
        for (int nt = 0; nt < 8; nt++) {
            mx0 = fmaxf(mx0, fmaxf(s[nt][0], s[nt][1]));
            mx1 = fmaxf(mx1, fmaxf(s[nt][2], s[nt][3]));
        }
        #pragma unroll
        for (int off = 1; off < 4; off <<= 1) {
            mx0 = fmaxf(mx0, __shfl_xor_sync(0xffffffffu, mx0, off));
            mx1 = fmaxf(mx1, __shfl_xor_sync(0xffffffffu, mx1, off));
        }
        float mn0 = fmaxf(m0, mx0), mn1 = fmaxf(m1, mx1);
        float c0 = __expf(m0 - mn0), c1 = __expf(m1 - mn1);
        m0 = mn0; m1 = mn1;

        float ls0 = 0.f, ls1 = 0.f;
        #pragma unroll
        for (int nt = 0; nt < 8; nt++) {
            float p00 = __expf(s[nt][0] - m0);
            float p01 = __expf(s[nt][1] - m0);
            float p10 = __expf(s[nt][2] - m1);
            float p11 = __expf(s[nt][3] - m1);
            ls0 += p00 + p01;          // unrounded sum (order preserved)
            ls1 += p10 + p11;
            uint2 pr0 = make_uint2(f2tf32(p00), f2tf32(p01));
            uint2 pr1 = make_uint2(f2tf32(p10), f2tf32(p11));
            *(uint2*)(Ps + g * PSTR + nt * 8 + 2 * t)       = pr0;
            *(uint2*)(Ps + (g + 8) * PSTR + nt * 8 + 2 * t) = pr1;
        }
        #pragma unroll
        for (int off = 1; off < 4; off <<= 1) {
            ls0 += __shfl_xor_sync(0xffffffffu, ls0, off);
            ls1 += __shfl_xor_sync(0xffffffffu, ls1, off);
        }
        l0 = l0 * c0 + ls0;
        l1 = l1 * c1 + ls1;
        #pragma unroll
        for (int nt = 0; nt < 16; nt++) {
            o[nt][0] *= c0; o[nt][1] *= c0;
            o[nt][2] *= c1; o[nt][3] *= c1;
        }
        __syncwarp();

        #pragma unroll
        for (int kk = 0; kk < 64; kk += 8) {
            unsigned pf[4];
            pf[0] = Pu[g * PSTR + kk + t];
            pf[1] = Pu[(g + 8) * PSTR + kk + t];
            pf[2] = Pu[g * PSTR + kk + 4 + t];
            pf[3] = Pu[(g + 8) * PSTR + kk + 4 + t];
            #pragma unroll
            for (int nt = 0; nt < 16; nt++) {
                unsigned bf[2];
                bf[0] = Vu[(kk + t) * VSTR + nt * 8 + g];
                bf[1] = Vu[(kk + 4 + t) * VSTR + nt * 8 + g];
                mma_tf32(o[nt], pf, bf);
            }
        }
        __syncwarp();
    }

    // store AO pre-rounded to tf32 (O-proj consumes directly)
    float inv0 = 1.f / l0, inv1 = 1.f / l1;
    int r0 = q0 + wrow + g, r1 = q0 + wrow + 8 + g;
    #pragma unroll
    for (int nt = 0; nt < 16; nt++) {
        int d = nt * 8 + 2 * t;
        float2 v0 = make_float2(
            __uint_as_float(f2tf32(o[nt][0] * inv0)),
            __uint_as_float(f2tf32(o[nt][1] * inv0)));
        float2 v1 = make_float2(
            __uint_as_float(f2tf32(o[nt][2] * inv1)),
            __uint_as_float(f2tf32(o[nt][3] * inv1)));
        *(float2*)(Og + base + (size_t)r0 * HID + d) = v0;
        *(float2*)(Og + base + (size_t)r1 * HID + d) = v1;
    }
}

// =====================================================================
// launcher
// =====================================================================
extern "C" void kernel_launch(void* const* d_in, const int* in_sizes, int n_in,
                              void* d_out, int out_size)
{
    const float* X   = (const float*)d_in[0];
    const float* qw  = (const float*)d_in[1];
    const float* qb  = (const float*)d_in[2];
    const float* kw  = (const float*)d_in[3];
    const float* kb  = (const float*)d_in[4];
    const float* vw  = (const float*)d_in[5];
    const float* vb  = (const float*)d_in[6];
    const float* ow  = (const float*)d_in[7];
    const float* ob  = (const float*)d_in[8];
    const float* qg  = (const float*)d_in[9];
    const float* qnb = (const float*)d_in[10];
    const float* kg  = (const float*)d_in[11];
    const float* knb = (const float*)d_in[12];
    float* out = (float*)d_out;

    float *Q, *K, *V, *AO, *Xr, *Wr;
    cudaGetSymbolAddress((void**)&Q,  g_Q);
    cudaGetSymbolAddress((void**)&K,  g_K);
    cudaGetSymbolAddress((void**)&V,  g_V);
    cudaGetSymbolAddress((void**)&AO, g_AO);
    cudaGetSymbolAddress((void**)&Xr, g_Xr);
    cudaGetSymbolAddress((void**)&Wr, g_Wr);
    float* qwr = Wr;
    float* kwr = Wr + (size_t)HID * HID;
    float* vwr = Wr + 2 * (size_t)HID * HID;
    float* owr = Wr + 3 * (size_t)HID * HID;

    cudaFuncSetAttribute(flash_attn_tc,
                         cudaFuncAttributeMaxDynamicSharedMemorySize,
                         FLASH_SMEM);
    cudaFuncSetAttribute(qkv_gemm,
                         cudaFuncAttributeMaxDynamicSharedMemorySize,
                         GEMM_SMEM);
    cudaFuncSetAttribute(tf32_gemm_bias,
                         cudaFuncAttributeMaxDynamicSharedMemorySize,
                         GEMM_SMEM);

    // prep: round X and weights to exact tf32 once
    round_prep<<<dim3(1024, 5), 256>>>(X, qw, kw, vw, ow,
                                       Xr, qwr, kwr, vwr, owr);

    // fused QKV projection: one launch, z selects q/k/v
    dim3 gq(HID / 128, NTOK / 128, 3);   // (16, 32, 3)
    qkv_gemm<<<gq, 128, GEMM_SMEM>>>(Xr, qwr, kwr, vwr, qb, kb, vb, Q, K, V);

    qk_ln<<<NTOK, 512>>>(Q, K, qg, qnb, kg, knb);

    flash_attn_tc<<<dim3(2048 / 128, 32), 256, FLASH_SMEM>>>(Q, K, V, AO);

    dim3 gg(HID / 128, NTOK / 128);      // (16, 32)
    tf32_gemm_bias<<<gg, 128, GEMM_SMEM>>>(AO, owr, ob, out);
}

// round 13
// speedup vs baseline: 1.0175x; 1.0175x over previous
#include <cuda_runtime.h>
#include <cstdint>
#include <math.h>

#define HID 2048
#define NTOK 4096
#define HEADS 16
#define HDIM 128

// ---- scratch (static device arrays; no allocations allowed) ----
__device__ float g_Q[NTOK * HID];
__device__ float g_K[NTOK * HID];
__device__ float g_V[NTOK * HID];
__device__ float g_AO[NTOK * HID];
__device__ float g_Xr[NTOK * HID];        // tf32-rounded hidden_states
__device__ float g_Wr[4][HID * HID];      // tf32-rounded weights (same layout)

// =====================================================================
// helpers
// =====================================================================
__device__ __forceinline__ unsigned f2tf32(float f) {
    unsigned u;
    asm("cvt.rna.tf32.f32 %0, %1;" : "=r"(u) : "f"(f));
    return u;
}
__device__ __forceinline__ void mma_tf32(float* c, const unsigned* a,
                                         const unsigned* b) {
    asm volatile(
        "mma.sync.aligned.m16n8k8.row.col.f32.tf32.tf32.f32 "
        "{%0,%1,%2,%3}, {%4,%5,%6,%7}, {%8,%9}, {%0,%1,%2,%3};\n"
        : "+f"(c[0]), "+f"(c[1]), "+f"(c[2]), "+f"(c[3])
        : "r"(a[0]), "r"(a[1]), "r"(a[2]), "r"(a[3]),
          "r"(b[0]), "r"(b[1]));
}
__device__ __forceinline__ void cp16(void* smem_dst, const void* g) {
    unsigned saddr = (unsigned)__cvta_generic_to_shared(smem_dst);
    asm volatile("cp.async.cg.shared.global [%0], [%1], 16;\n"
                 :: "r"(saddr), "l"(g));
}
__device__ __forceinline__ void cp_commit() {
    asm volatile("cp.async.commit_group;\n");
}
__device__ __forceinline__ void cp_wait1() {
    asm volatile("cp.async.wait_group 1;\n");
}
__device__ __forceinline__ void cp_wait0() {
    asm volatile("cp.async.wait_group 0;\n");
}

// =====================================================================
// prep: round X and the 4 weights to exact tf32 values (rna), in gmem.
// =====================================================================
__global__ __launch_bounds__(256)
void round_prep(const float* __restrict__ X,
                const float* __restrict__ w0, const float* __restrict__ w1,
                const float* __restrict__ w2, const float* __restrict__ w3,
                float* __restrict__ Xr,
                float* __restrict__ r0, float* __restrict__ r1,
                float* __restrict__ r2, float* __restrict__ r3)
{
    int z = blockIdx.y;
    const float4* src;
    float4* dst;
    int n4;
    if (z == 0)      { src = (const float4*)X;  dst = (float4*)Xr; n4 = NTOK * HID / 4; }
    else if (z == 1) { src = (const float4*)w0; dst = (float4*)r0; n4 = HID * HID / 4; }
    else if (z == 2) { src = (const float4*)w1; dst = (float4*)r1; n4 = HID * HID / 4; }
    else if (z == 3) { src = (const float4*)w2; dst = (float4*)r2; n4 = HID * HID / 4; }
    else             { src = (const float4*)w3; dst = (float4*)r3; n4 = HID * HID / 4; }

    int i = blockIdx.x * blockDim.x + threadIdx.x;
    int stride = gridDim.x * blockDim.x;
    for (; i < n4; i += stride) {
        float4 v = src[i];
        v.x = __uint_as_float(f2tf32(v.x));
        v.y = __uint_as_float(f2tf32(v.y));
        v.z = __uint_as_float(f2tf32(v.z));
        v.w = __uint_as_float(f2tf32(v.w));
        dst[i] = v;
    }
}

// =====================================================================
// TF32 tensor-core GEMM with bias (pre-rounded inputs, no mainloop cvt)
// 128x128x32 block tile, 128 threads (4 warps, 2x2), warp tile 64x64.
// =====================================================================
#define ASTR 36
#define BSTR 136
#define GEMM_SMEM ((2 * 128 * ASTR + 2 * 32 * BSTR) * 4)   // 71680 B

__device__ __forceinline__
void gemm_body(const float* __restrict__ A, const float* __restrict__ B,
               const float* __restrict__ bias, float* __restrict__ C)
{
    extern __shared__ float gsm[];
    float* Asm[2] = { gsm, gsm + 128 * ASTR };
    float* Bsm[2] = { gsm + 2 * 128 * ASTR, gsm + 2 * 128 * ASTR + 32 * BSTR };

    const int tid  = threadIdx.x;
    const int lane = tid & 31;
    const int g    = lane >> 2;
    const int t    = lane & 3;
    const int wid  = tid >> 5;
    const int warpM = wid & 1;
    const int warpN = wid >> 1;
    const int row0 = blockIdx.y * 128;
    const int col0 = blockIdx.x * 128;

    float acc[4][8][4];
    #pragma unroll
    for (int i = 0; i < 4; i++)
        #pragma unroll
        for (int j = 0; j < 8; j++)
            #pragma unroll
            for (int c = 0; c < 4; c++) acc[i][j][c] = 0.f;

    const int nk = HID >> 5;

    #define LOAD_TILE(bufi, kt_) { \
        const float* ag = A + (size_t)row0 * HID + (kt_) * 32; \
        _Pragma("unroll") \
        for (int j = 0; j < 8; j++) { \
            int idx = j * 128 + tid; \
            int r = idx >> 3, c = (idx & 7) * 4; \
            cp16(&Asm[bufi][r * ASTR + c], ag + (size_t)r * HID + c); \
        } \
        const float* bg = B + (size_t)((kt_) * 32) * HID + col0; \
        _Pragma("unroll") \
        for (int j = 0; j < 8; j++) { \
            int idx = j * 128 + tid; \
            int kr = idx >> 5, n = (idx & 31) * 4; \
            cp16(&Bsm[bufi][kr * BSTR + n], bg + (size_t)kr * HID + n); \
        } \
        cp_commit(); }

    LOAD_TILE(0, 0);

    int buf = 0;
    for (int kt = 0; kt < nk; kt++) {
        if (kt + 1 < nk) {
            LOAD_TILE(buf ^ 1, kt + 1);
            cp_wait1();
        } else {
            cp_wait0();
        }
        __syncthreads();

        const unsigned* as = (const unsigned*)Asm[buf];
        const unsigned* bs = (const unsigned*)Bsm[buf];

        #pragma unroll
        for (int kk = 0; kk < 32; kk += 8) {
            unsigned bf[8][2];
            #pragma unroll
            for (int tn = 0; tn < 8; tn++) {
                int n = warpN * 64 + tn * 8 + g;
                bf[tn][0] = bs[(kk +     t) * BSTR + n];
                bf[tn][1] = bs[(kk + 4 + t) * BSTR + n];
            }
            unsigned af[4][4];
            #pragma unroll
            for (int tm = 0; tm < 4; tm++) {
                int m = warpM * 64 + tm * 16 + g;
                af[tm][0] = as[m * ASTR + kk + t];
                af[tm][1] = as[(m + 8) * ASTR + kk + t];
                af[tm][2] = as[m * ASTR + kk + 4 + t];
                af[tm][3] = as[(m + 8) * ASTR + kk + 4 + t];
            }
            #pragma unroll
            for (int tm = 0; tm < 4; tm++)
                #pragma unroll
                for (int tn = 0; tn < 8; tn++)
                    mma_tf32(acc[tm][tn], af[tm], bf[tn]);
        }
        __syncthreads();
        buf ^= 1;
    }
    #undef LOAD_TILE

    #pragma unroll
    for (int tm = 0; tm < 4; tm++) {
        int mrow = row0 + warpM * 64 + tm * 16 + g;
        #pragma unroll
        for (int tn = 0; tn < 8; tn++) {
            int ncol = col0 + warpN * 64 + tn * 8 + t * 2;
            float b0 = bias[ncol], b1 = bias[ncol + 1];
            float2 v0 = make_float2(acc[tm][tn][0] + b0, acc[tm][tn][1] + b1);
            float2 v1 = make_float2(acc[tm][tn][2] + b0, acc[tm][tn][3] + b1);
            *(float2*)(C + (size_t)mrow * HID + ncol) = v0;
            *(float2*)(C + (size_t)(mrow + 8) * HID + ncol) = v1;
        }
    }
}

__global__ __launch_bounds__(128)
void qkv_gemm(const float* __restrict__ A,
              const float* __restrict__ W0, const float* __restrict__ W1,
              const float* __restrict__ W2,
              const float* __restrict__ b0, const float* __restrict__ b1,
              const float* __restrict__ b2,
              float* __restrict__ C0, float* __restrict__ C1,
              float* __restrict__ C2)
{
    const float* W = (blockIdx.z == 0) ? W0 : (blockIdx.z == 1) ? W1 : W2;
    const float* b = (blockIdx.z == 0) ? b0 : (blockIdx.z == 1) ? b1 : b2;
    float*       C = (blockIdx.z == 0) ? C0 : (blockIdx.z == 1) ? C1 : C2;
    gemm_body(A, W, b, C);
}

__global__ __launch_bounds__(128)
void tf32_gemm_bias(const float* __restrict__ A, const float* __restrict__ B,
                    const float* __restrict__ bias, float* __restrict__ C)
{
    gemm_body(A, B, bias, C);
}

// =====================================================================
// Per-head LayerNorm over head_dim=128 for Q and K (in place).
// =====================================================================
__device__ __forceinline__ void ln_head(float* p, const float* g,
                                        const float* be, int lane)
{
    float4 x = *(float4*)(p + lane * 4);
    float s  = x.x + x.y + x.z + x.w;
    float ss = x.x * x.x + x.y * x.y + x.z * x.z + x.w * x.w;
    #pragma unroll
    for (int off = 16; off > 0; off >>= 1) {
        s  += __shfl_xor_sync(0xffffffffu, s,  off);
        ss += __shfl_xor_sync(0xffffffffu, ss, off);
    }
    float mean = s * (1.f / 128.f);
    float var  = ss * (1.f / 128.f) - mean * mean;
    float rstd = rsqrtf(var + 1e-6f);
    float4 gg = *(const float4*)(g  + lane * 4);
    float4 bb = *(const float4*)(be + lane * 4);
    x.x = (x.x - mean) * rstd * gg.x + bb.x;
    x.y = (x.y - mean) * rstd * gg.y + bb.y;
    x.z = (x.z - mean) * rstd * gg.z + bb.z;
    x.w = (x.w - mean) * rstd * gg.w + bb.w;
    *(float4*)(p + lane * 4) = x;
}

__global__ __launch_bounds__(512)
void qk_ln(float* __restrict__ Q, float* __restrict__ K,
           const float* __restrict__ qg, const float* __restrict__ qb,
           const float* __restrict__ kg, const float* __restrict__ kb)
{
    int tk = blockIdx.x;
    int h = threadIdx.x >> 5;
    int lane = threadIdx.x & 31;
    ln_head(Q + (size_t)tk * HID + h * HDIM, qg, qb, lane);
    ln_head(K + (size_t)tk * HID + h * HDIM, kg, kb, lane);
}

// =====================================================================
// Tensor-core flash attention — split-key warp pairs.
// 512 threads = 16 warps. Warp w: wq = w&7 (Q rows wq*16..+15),
// wk = w>>3 (key half: keys wk*32..wk*32+31 of each 64-key tile).
// Each warp runs exact online softmax over its disjoint key subsequence;
// one exact pair-merge at the end through smem.
// All smem operands pre-rounded tf32 (bare LDS + MMA inner loops).
// =====================================================================
#define QSTR 132
#define KSTR 132
#define VSTR 136
#define PSTR2 36
// merge buffer (reuses K/V/P region): 8 pairs x 32 lanes x 68 floats
#define KVP_BYTES ((64 * KSTR + 64 * VSTR + 16 * 16 * PSTR2) * 4)
#define MERGE_BYTES (8 * 32 * 68 * 4)
#define FLASH_SMEM (128 * QSTR * 4 + (KVP_BYTES > MERGE_BYTES ? KVP_BYTES : MERGE_BYTES))

__global__ __launch_bounds__(512)
void flash_attn_tc(const float* __restrict__ Qg, const float* __restrict__ Kg,
                   const float* __restrict__ Vg, float* __restrict__ Og)
{
    extern __shared__ float sm[];
    float* Qs = sm;                       // 128 x QSTR
    float* Ks = Qs + 128 * QSTR;          // 64 x KSTR
    float* Vs = Ks + 64 * KSTR;           // 64 x VSTR
    float* Pw = Vs + 64 * VSTR;           // 16 warps x 16 x PSTR2
    float* Mb = Ks;                       // merge buffer aliases K/V/P

    const int tid  = threadIdx.x;
    const int lane = tid & 31;
    const int w    = tid >> 5;            // 0..15
    const int wq   = w & 7;               // Q-row group
    const int wk   = w >> 3;              // key half 0/1
    const int g    = lane >> 2;
    const int t    = lane & 3;
    const int bh = blockIdx.y;
    const int b  = bh >> 4, h = bh & 15;
    const int q0 = blockIdx.x * 128;
    const size_t base = (size_t)b * 2048 * HID + (size_t)h * HDIM;
    const float scale = 0.08838834764831845f;

    float* Ps = Pw + w * 16 * PSTR2;
    const int wrow = wq * 16;
    const int koff = wk * 32;             // warp's key offset within tile

    // Q tile: scale then round to tf32 once
    for (int i = tid; i < 128 * 32; i += 512) {
        int r = i >> 5, c4 = (i & 31) << 2;
        float4 q = *(const float4*)(Qg + base + (size_t)(q0 + r) * HID + c4);
        uint4 qu;
        qu.x = f2tf32(q.x * scale);
        qu.y = f2tf32(q.y * scale);
        qu.z = f2tf32(q.z * scale);
        qu.w = f2tf32(q.w * scale);
        *(uint4*)(Qs + r * QSTR + c4) = qu;
    }

    float m0 = -1e30f, m1 = -1e30f, l0 = 0.f, l1 = 0.f;
    float o[16][4];
    #pragma unroll
    for (int nt = 0; nt < 16; nt++)
        #pragma unroll
        for (int c = 0; c < 4; c++) o[nt][c] = 0.f;

    for (int kt = 0; kt < 2048 / 64; kt++) {
        const int k0 = kt * 64;
        __syncthreads();
        // K/V tiles rounded at store
        for (int i = tid; i < 64 * 32; i += 512) {
            int r = i >> 5, c4 = (i & 31) << 2;
            float4 kv = *(const float4*)(Kg + base + (size_t)(k0 + r) * HID + c4);
            uint4 ku;
            ku.x = f2tf32(kv.x); ku.y = f2tf32(kv.y);
            ku.z = f2tf32(kv.z); ku.w = f2tf32(kv.w);
            *(uint4*)(Ks + r * KSTR + c4) = ku;
            float4 vv = *(const float4*)(Vg + base + (size_t)(k0 + r) * HID + c4);
            uint4 vu;
            vu.x = f2tf32(vv.x); vu.y = f2tf32(vv.y);
            vu.z = f2tf32(vv.z); vu.w = f2tf32(vv.w);
            *(uint4*)(Vs + r * VSTR + c4) = vu;
        }
        __syncthreads();

        const unsigned* Qu = (const unsigned*)Qs;
        const unsigned* Ku = (const unsigned*)Ks;
        const unsigned* Vu = (const unsigned*)Vs;
        const unsigned* Pu = (const unsigned*)Ps;

        // ---- S = Q_tile(16) x K_half(32)^T ----
        float s[4][4];
        #pragma unroll
        for (int nt = 0; nt < 4; nt++)
            #pragma unroll
            for (int c = 0; c < 4; c++) s[nt][c] = 0.f;

        #pragma unroll
        for (int kk = 0; kk < 128; kk += 8) {
            unsigned af[4];
            af[0] = Qu[(wrow + g) * QSTR + kk + t];
            af[1] = Qu[(wrow + 8 + g) * QSTR + kk + t];
            af[2] = Qu[(wrow + g) * QSTR + kk + 4 + t];
            af[3] = Qu[(wrow + 8 + g) * QSTR + kk + 4 + t];
            #pragma unroll
            for (int nt = 0; nt < 4; nt++) {
                unsigned bf[2];
                bf[0] = Ku[(koff + nt * 8 + g) * KSTR + kk + t];
                bf[1] = Ku[(koff + nt * 8 + g) * KSTR + kk + 4 + t];
                mma_tf32(s[nt], af, bf);
            }
        }

        // ---- online softmax over this warp's 32 keys ----
        float mx0 = -1e30f, mx1 = -1e30f;
        #pragma unroll
        for (int nt = 0; nt < 4; nt++) {
            mx0 = fmaxf(mx0, fmaxf(s[nt][0], s[nt][1]));
            mx1 = fmaxf(mx1, fmaxf(s[nt][2], s[nt][3]));
        }
        #pragma unroll
        for (int off = 1; off < 4; off <<= 1) {
            mx0 = fmaxf(mx0, __shfl_xor_sync(0xffffffffu, mx0, off));
            mx1 = fmaxf(mx1, __shfl_xor_sync(0xffffffffu, mx1, off));
        }
        float mn0 = fmaxf(m0, mx0), mn1 = fmaxf(m1, mx1);
        float c0 = __expf(m0 - mn0), c1 = __expf(m1 - mn1);
        m0 = mn0; m1 = mn1;

        float ls0 = 0.f, ls1 = 0.f;
        #pragma unroll
        for (int nt = 0; nt < 4; nt++) {
            float p00 = __expf(s[nt][0] - m0);
            float p01 = __expf(s[nt][1] - m0);
            float p10 = __expf(s[nt][2] - m1);
            float p11 = __expf(s[nt][3] - m1);
            ls0 += p00 + p01;
            ls1 += p10 + p11;
            uint2 pr0 = make_uint2(f2tf32(p00), f2tf32(p01));
            uint2 pr1 = make_uint2(f2tf32(p10), f2tf32(p11));
            *(uint2*)(Ps + g * PSTR2 + nt * 8 + 2 * t)       = pr0;
            *(uint2*)(Ps + (g + 8) * PSTR2 + nt * 8 + 2 * t) = pr1;
        }
        #pragma unroll
        for (int off = 1; off < 4; off <<= 1) {
            ls0 += __shfl_xor_sync(0xffffffffu, ls0, off);
            ls1 += __shfl_xor_sync(0xffffffffu, ls1, off);
        }
        l0 = l0 * c0 + ls0;
        l1 = l1 * c1 + ls1;
        #pragma unroll
        for (int nt = 0; nt < 16; nt++) {
            o[nt][0] *= c0; o[nt][1] *= c0;
            o[nt][2] *= c1; o[nt][3] *= c1;
        }
        __syncwarp();

        // ---- O += P(16x32) x V_half(32x128) ----
        #pragma unroll
        for (int kk = 0; kk < 32; kk += 8) {
            unsigned pf[4];
            pf[0] = Pu[g * PSTR2 + kk + t];
            pf[1] = Pu[(g + 8) * PSTR2 + kk + t];
            pf[2] = Pu[g * PSTR2 + kk + 4 + t];
            pf[3] = Pu[(g + 8) * PSTR2 + kk + 4 + t];
            #pragma unroll
            for (int nt = 0; nt < 16; nt++) {
                unsigned bf[2];
                bf[0] = Vu[(koff + kk + t) * VSTR + nt * 8 + g];
                bf[1] = Vu[(koff + kk + 4 + t) * VSTR + nt * 8 + g];
                mma_tf32(o[nt], pf, bf);
            }
        }
        __syncwarp();
    }

    // ---- pair merge: warp wq (wk=0) combines with warp wq+8 (wk=1) ----
    __syncthreads();                      // all K/V/P use finished
    if (wk == 1) {
        float* dst = Mb + (wq * 32 + lane) * 68;
        #pragma unroll
        for (int nt = 0; nt < 16; nt++) {
            dst[nt * 4 + 0] = o[nt][0];
            dst[nt * 4 + 1] = o[nt][1];
            dst[nt * 4 + 2] = o[nt][2];
            dst[nt * 4 + 3] = o[nt][3];
        }
        dst[64] = m0; dst[65] = l0; dst[66] = m1; dst[67] = l1;
    }
    __syncthreads();
    if (wk == 0) {
        const float* src = Mb + (wq * 32 + lane) * 68;
        float pm0 = src[64], pl0 = src[65], pm1 = src[66], pl1 = src[67];
        float M0 = fmaxf(m0, pm0), M1 = fmaxf(m1, pm1);
        float a0 = __expf(m0 - M0), b0 = __expf(pm0 - M0);
        float a1 = __expf(m1 - M1), b1 = __expf(pm1 - M1);
        float inv0 = 1.f / (a0 * l0 + b0 * pl0);
        float inv1 = 1.f / (a1 * l1 + b1 * pl1);
        int r0 = q0 + wrow + g, r1 = q0 + wrow + 8 + g;
        #pragma unroll
        for (int nt = 0; nt < 16; nt++) {
            int d = nt * 8 + 2 * t;
            float o00 = (a0 * o[nt][0] + b0 * src[nt * 4 + 0]) * inv0;
            float o01 = (a0 * o[nt][1] + b0 * src[nt * 4 + 1]) * inv0;
            float o10 = (a1 * o[nt][2] + b1 * src[nt * 4 + 2]) * inv1;
            float o11 = (a1 * o[nt][3] + b1 * src[nt * 4 + 3]) * inv1;
            float2 v0 = make_float2(__uint_as_float(f2tf32(o00)),
                                    __uint_as_float(f2tf32(o01)));
            float2 v1 = make_float2(__uint_as_float(f2tf32(o10)),
                                    __uint_as_float(f2tf32(o11)));
            *(float2*)(Og + base + (size_t)r0 * HID + d) = v0;
            *(float2*)(Og + base + (size_t)r1 * HID + d) = v1;
        }
    }
}

// =====================================================================
// launcher
// =====================================================================
extern "C" void kernel_launch(void* const* d_in, const int* in_sizes, int n_in,
                              void* d_out, int out_size)
{
    const float* X   = (const float*)d_in[0];
    const float* qw  = (const float*)d_in[1];
    const float* qb  = (const float*)d_in[2];
    const float* kw  = (const float*)d_in[3];
    const float* kb  = (const float*)d_in[4];
    const float* vw  = (const float*)d_in[5];
    const float* vb  = (const float*)d_in[6];
    const float* ow  = (const float*)d_in[7];
    const float* ob  = (const float*)d_in[8];
    const float* qg  = (const float*)d_in[9];
    const float* qnb = (const float*)d_in[10];
    const float* kg  = (const float*)d_in[11];
    const float* knb = (const float*)d_in[12];
    float* out = (float*)d_out;

    float *Q, *K, *V, *AO, *Xr, *Wr;
    cudaGetSymbolAddress((void**)&Q,  g_Q);
    cudaGetSymbolAddress((void**)&K,  g_K);
    cudaGetSymbolAddress((void**)&V,  g_V);
    cudaGetSymbolAddress((void**)&AO, g_AO);
    cudaGetSymbolAddress((void**)&Xr, g_Xr);
    cudaGetSymbolAddress((void**)&Wr, g_Wr);
    float* qwr = Wr;
    float* kwr = Wr + (size_t)HID * HID;
    float* vwr = Wr + 2 * (size_t)HID * HID;
    float* owr = Wr + 3 * (size_t)HID * HID;

    cudaFuncSetAttribute(flash_attn_tc,
                         cudaFuncAttributeMaxDynamicSharedMemorySize,
                         FLASH_SMEM);
    cudaFuncSetAttribute(qkv_gemm,
                         cudaFuncAttributeMaxDynamicSharedMemorySize,
                         GEMM_SMEM);
    cudaFuncSetAttribute(tf32_gemm_bias,
                         cudaFuncAttributeMaxDynamicSharedMemorySize,
                         GEMM_SMEM);

    // prep: round X and weights to exact tf32 once
    round_prep<<<dim3(1024, 5), 256>>>(X, qw, kw, vw, ow,
                                       Xr, qwr, kwr, vwr, owr);

    // fused QKV projection: one launch, z selects q/k/v
    dim3 gq(HID / 128, NTOK / 128, 3);   // (16, 32, 3)
    qkv_gemm<<<gq, 128, GEMM_SMEM>>>(Xr, qwr, kwr, vwr, qb, kb, vb, Q, K, V);

    qk_ln<<<NTOK, 512>>>(Q, K, qg, qnb, kg, knb);

    flash_attn_tc<<<dim3(2048 / 128, 32), 512, FLASH_SMEM>>>(Q, K, V, AO);

    dim3 gg(HID / 128, NTOK / 128);      // (16, 32)
    tf32_gemm_bias<<<gg, 128, GEMM_SMEM>>>(AO, owr, ob, out);
}

// round 14
// speedup vs baseline: 1.1293x; 1.1099x over previous
#include <cuda_runtime.h>
#include <cstdint>
#include <math.h>

#define HID 2048
#define NTOK 4096
#define HEADS 16
#define HDIM 128

// ---- scratch (static device arrays; no allocations allowed) ----
__device__ float g_Q[NTOK * HID];
__device__ float g_K[NTOK * HID];
__device__ float g_V[NTOK * HID];
__device__ float g_AO[NTOK * HID];
__device__ float g_Xr[NTOK * HID];        // tf32-rounded hidden_states
__device__ float g_Wr[4][HID * HID];      // tf32-rounded weights (same layout)

// =====================================================================
// helpers
// =====================================================================
__device__ __forceinline__ unsigned f2tf32(float f) {
    unsigned u;
    asm("cvt.rna.tf32.f32 %0, %1;" : "=r"(u) : "f"(f));
    return u;
}
__device__ __forceinline__ void mma_tf32(float* c, const unsigned* a,
                                         const unsigned* b) {
    asm volatile(
        "mma.sync.aligned.m16n8k8.row.col.f32.tf32.tf32.f32 "
        "{%0,%1,%2,%3}, {%4,%5,%6,%7}, {%8,%9}, {%0,%1,%2,%3};\n"
        : "+f"(c[0]), "+f"(c[1]), "+f"(c[2]), "+f"(c[3])
        : "r"(a[0]), "r"(a[1]), "r"(a[2]), "r"(a[3]),
          "r"(b[0]), "r"(b[1]));
}
__device__ __forceinline__ void cp16(void* smem_dst, const void* g) {
    unsigned saddr = (unsigned)__cvta_generic_to_shared(smem_dst);
    asm volatile("cp.async.cg.shared.global [%0], [%1], 16;\n"
                 :: "r"(saddr), "l"(g));
}
__device__ __forceinline__ void cp_commit() {
    asm volatile("cp.async.commit_group;\n");
}
__device__ __forceinline__ void cp_wait1() {
    asm volatile("cp.async.wait_group 1;\n");
}
__device__ __forceinline__ void cp_wait0() {
    asm volatile("cp.async.wait_group 0;\n");
}

// =====================================================================
// prep: round X and the 4 weights to exact tf32 values (rna), in gmem.
// =====================================================================
__global__ __launch_bounds__(256)
void round_prep(const float* __restrict__ X,
                const float* __restrict__ w0, const float* __restrict__ w1,
                const float* __restrict__ w2, const float* __restrict__ w3,
                float* __restrict__ Xr,
                float* __restrict__ r0, float* __restrict__ r1,
                float* __restrict__ r2, float* __restrict__ r3)
{
    int z = blockIdx.y;
    const float4* src;
    float4* dst;
    int n4;
    if (z == 0)      { src = (const float4*)X;  dst = (float4*)Xr; n4 = NTOK * HID / 4; }
    else if (z == 1) { src = (const float4*)w0; dst = (float4*)r0; n4 = HID * HID / 4; }
    else if (z == 2) { src = (const float4*)w1; dst = (float4*)r1; n4 = HID * HID / 4; }
    else if (z == 3) { src = (const float4*)w2; dst = (float4*)r2; n4 = HID * HID / 4; }
    else             { src = (const float4*)w3; dst = (float4*)r3; n4 = HID * HID / 4; }

    int i = blockIdx.x * blockDim.x + threadIdx.x;
    int stride = gridDim.x * blockDim.x;
    for (; i < n4; i += stride) {
        float4 v = src[i];
        v.x = __uint_as_float(f2tf32(v.x));
        v.y = __uint_as_float(f2tf32(v.y));
        v.z = __uint_as_float(f2tf32(v.z));
        v.w = __uint_as_float(f2tf32(v.w));
        dst[i] = v;
    }
}

// =====================================================================
// TF32 tensor-core GEMM with bias (pre-rounded inputs, no mainloop cvt)
// 128x128x32 block tile, 128 threads (4 warps, 2x2), warp tile 64x64.
// =====================================================================
#define ASTR 36
#define BSTR 136
#define GEMM_SMEM ((2 * 128 * ASTR + 2 * 32 * BSTR) * 4)   // 71680 B

__device__ __forceinline__
void gemm_body(const float* __restrict__ A, const float* __restrict__ B,
               const float* __restrict__ bias, float* __restrict__ C)
{
    extern __shared__ float gsm[];
    float* Asm[2] = { gsm, gsm + 128 * ASTR };
    float* Bsm[2] = { gsm + 2 * 128 * ASTR, gsm + 2 * 128 * ASTR + 32 * BSTR };

    const int tid  = threadIdx.x;
    const int lane = tid & 31;
    const int g    = lane >> 2;
    const int t    = lane & 3;
    const int wid  = tid >> 5;
    const int warpM = wid & 1;
    const int warpN = wid >> 1;
    const int row0 = blockIdx.y * 128;
    const int col0 = blockIdx.x * 128;

    float acc[4][8][4];
    #pragma unroll
    for (int i = 0; i < 4; i++)
        #pragma unroll
        for (int j = 0; j < 8; j++)
            #pragma unroll
            for (int c = 0; c < 4; c++) acc[i][j][c] = 0.f;

    const int nk = HID >> 5;

    #define LOAD_TILE(bufi, kt_) { \
        const float* ag = A + (size_t)row0 * HID + (kt_) * 32; \
        _Pragma("unroll") \
        for (int j = 0; j < 8; j++) { \
            int idx = j * 128 + tid; \
            int r = idx >> 3, c = (idx & 7) * 4; \
            cp16(&Asm[bufi][r * ASTR + c], ag + (size_t)r * HID + c); \
        } \
        const float* bg = B + (size_t)((kt_) * 32) * HID + col0; \
        _Pragma("unroll") \
        for (int j = 0; j < 8; j++) { \
            int idx = j * 128 + tid; \
            int kr = idx >> 5, n = (idx & 31) * 4; \
            cp16(&Bsm[bufi][kr * BSTR + n], bg + (size_t)kr * HID + n); \
        } \
        cp_commit(); }

    LOAD_TILE(0, 0);

    int buf = 0;
    for (int kt = 0; kt < nk; kt++) {
        if (kt + 1 < nk) {
            LOAD_TILE(buf ^ 1, kt + 1);
            cp_wait1();
        } else {
            cp_wait0();
        }
        __syncthreads();

        const unsigned* as = (const unsigned*)Asm[buf];
        const unsigned* bs = (const unsigned*)Bsm[buf];

        #pragma unroll
        for (int kk = 0; kk < 32; kk += 8) {
            unsigned bf[8][2];
            #pragma unroll
            for (int tn = 0; tn < 8; tn++) {
                int n = warpN * 64 + tn * 8 + g;
                bf[tn][0] = bs[(kk +     t) * BSTR + n];
                bf[tn][1] = bs[(kk + 4 + t) * BSTR + n];
            }
            unsigned af[4][4];
            #pragma unroll
            for (int tm = 0; tm < 4; tm++) {
                int m = warpM * 64 + tm * 16 + g;
                af[tm][0] = as[m * ASTR + kk + t];
                af[tm][1] = as[(m + 8) * ASTR + kk + t];
                af[tm][2] = as[m * ASTR + kk + 4 + t];
                af[tm][3] = as[(m + 8) * ASTR + kk + 4 + t];
            }
            #pragma unroll
            for (int tm = 0; tm < 4; tm++)
                #pragma unroll
                for (int tn = 0; tn < 8; tn++)
                    mma_tf32(acc[tm][tn], af[tm], bf[tn]);
        }
        __syncthreads();
        buf ^= 1;
    }
    #undef LOAD_TILE

    #pragma unroll
    for (int tm = 0; tm < 4; tm++) {
        int mrow = row0 + warpM * 64 + tm * 16 + g;
        #pragma unroll
        for (int tn = 0; tn < 8; tn++) {
            int ncol = col0 + warpN * 64 + tn * 8 + t * 2;
            float b0 = bias[ncol], b1 = bias[ncol + 1];
            float2 v0 = make_float2(acc[tm][tn][0] + b0, acc[tm][tn][1] + b1);
            float2 v1 = make_float2(acc[tm][tn][2] + b0, acc[tm][tn][3] + b1);
            *(float2*)(C + (size_t)mrow * HID + ncol) = v0;
            *(float2*)(C + (size_t)(mrow + 8) * HID + ncol) = v1;
        }
    }
}

__global__ __launch_bounds__(128)
void qkv_gemm(const float* __restrict__ A,
              const float* __restrict__ W0, const float* __restrict__ W1,
              const float* __restrict__ W2,
              const float* __restrict__ b0, const float* __restrict__ b1,
              const float* __restrict__ b2,
              float* __restrict__ C0, float* __restrict__ C1,
              float* __restrict__ C2)
{
    const float* W = (blockIdx.z == 0) ? W0 : (blockIdx.z == 1) ? W1 : W2;
    const float* b = (blockIdx.z == 0) ? b0 : (blockIdx.z == 1) ? b1 : b2;
    float*       C = (blockIdx.z == 0) ? C0 : (blockIdx.z == 1) ? C1 : C2;
    gemm_body(A, W, b, C);
}

__global__ __launch_bounds__(128)
void tf32_gemm_bias(const float* __restrict__ A, const float* __restrict__ B,
                    const float* __restrict__ bias, float* __restrict__ C)
{
    gemm_body(A, B, bias, C);
}

// =====================================================================
// Per-head LayerNorm over head_dim=128 for Q and K (in place).
// =====================================================================
__device__ __forceinline__ void ln_head(float* p, const float* g,
                                        const float* be, int lane)
{
    float4 x = *(float4*)(p + lane * 4);
    float s  = x.x + x.y + x.z + x.w;
    float ss = x.x * x.x + x.y * x.y + x.z * x.z + x.w * x.w;
    #pragma unroll
    for (int off = 16; off > 0; off >>= 1) {
        s  += __shfl_xor_sync(0xffffffffu, s,  off);
        ss += __shfl_xor_sync(0xffffffffu, ss, off);
    }
    float mean = s * (1.f / 128.f);
    float var  = ss * (1.f / 128.f) - mean * mean;
    float rstd = rsqrtf(var + 1e-6f);
    float4 gg = *(const float4*)(g  + lane * 4);
    float4 bb = *(const float4*)(be + lane * 4);
    x.x = (x.x - mean) * rstd * gg.x + bb.x;
    x.y = (x.y - mean) * rstd * gg.y + bb.y;
    x.z = (x.z - mean) * rstd * gg.z + bb.z;
    x.w = (x.w - mean) * rstd * gg.w + bb.w;
    *(float4*)(p + lane * 4) = x;
}

__global__ __launch_bounds__(512)
void qk_ln(float* __restrict__ Q, float* __restrict__ K,
           const float* __restrict__ qg, const float* __restrict__ qb,
           const float* __restrict__ kg, const float* __restrict__ kb)
{
    int tk = blockIdx.x;
    int h = threadIdx.x >> 5;
    int lane = threadIdx.x & 31;
    ln_head(Q + (size_t)tk * HID + h * HDIM, qg, qb, lane);
    ln_head(K + (size_t)tk * HID + h * HDIM, kg, kb, lane);
}

// =====================================================================
// Tensor-core flash attention — R10 body + cp.async split K/V pipeline.
// 256 threads = 8 warps; warp w owns Q rows w*16..w*16+15.
// Schedule: K[i+1] load overlaps PV_i; V[i+1] load overlaps S_{i+1}.
// K/V in smem raw; fragments convert via cvt.rna at load (bit-identical
// to rounding at store). Q and P stored pre-rounded.
// =====================================================================
#define QSTR 132
#define KSTR 132
#define VSTR 136
#define PSTR 68
#define FLASH_SMEM ((128 * QSTR + 64 * KSTR + 64 * VSTR + 8 * 16 * PSTR) * 4)
#define NKT_ATT (2048 / 64)

__global__ __launch_bounds__(256)
void flash_attn_tc(const float* __restrict__ Qg, const float* __restrict__ Kg,
                   const float* __restrict__ Vg, float* __restrict__ Og)
{
    extern __shared__ float sm[];
    float* Qs = sm;                       // 128 x QSTR (pre-rounded tf32 bits)
    float* Ks = Qs + 128 * QSTR;          // 64 x KSTR  (raw)
    float* Vs = Ks + 64 * KSTR;           // 64 x VSTR  (raw)
    float* Pw = Vs + 64 * VSTR;           // 8 x 16 x PSTR (pre-rounded)

    const int tid  = threadIdx.x;
    const int lane = tid & 31;
    const int w    = tid >> 5;
    const int g    = lane >> 2;
    const int t    = lane & 3;
    const int bh = blockIdx.y;
    const int b  = bh >> 4, h = bh & 15;
    const int q0 = blockIdx.x * 128;
    const size_t base = (size_t)b * 2048 * HID + (size_t)h * HDIM;
    const float scale = 0.08838834764831845f;

    float* Ps = Pw + w * 16 * PSTR;
    const int wrow = w * 16;

    // K/V tile issue: 64 rows x 32 float4; thread does i = j*256+tid
    #define ISSUE_K(kt_) { \
        const float* src = Kg + base + (size_t)((kt_) * 64) * HID; \
        _Pragma("unroll") \
        for (int j = 0; j < 8; j++) { \
            int i = j * 256 + tid; \
            int r = i >> 5, c4 = (i & 31) << 2; \
            cp16(Ks + r * KSTR + c4, src + (size_t)r * HID + c4); \
        } \
        cp_commit(); }
    #define ISSUE_V(kt_) { \
        const float* src = Vg + base + (size_t)((kt_) * 64) * HID; \
        _Pragma("unroll") \
        for (int j = 0; j < 8; j++) { \
            int i = j * 256 + tid; \
            int r = i >> 5, c4 = (i & 31) << 2; \
            cp16(Vs + r * VSTR + c4, src + (size_t)r * HID + c4); \
        } \
        cp_commit(); }

    // prologue: K0, V0 in flight; Q load overlaps them
    ISSUE_K(0);
    ISSUE_V(0);
    for (int i = tid; i < 128 * 32; i += 256) {
        int r = i >> 5, c4 = (i & 31) << 2;
        float4 q = *(const float4*)(Qg + base + (size_t)(q0 + r) * HID + c4);
        uint4 qu;
        qu.x = f2tf32(q.x * scale);
        qu.y = f2tf32(q.y * scale);
        qu.z = f2tf32(q.z * scale);
        qu.w = f2tf32(q.w * scale);
        *(uint4*)(Qs + r * QSTR + c4) = qu;
    }

    float m0 = -1e30f, m1 = -1e30f, l0 = 0.f, l1 = 0.f;
    float o[16][4];
    #pragma unroll
    for (int nt = 0; nt < 16; nt++)
        #pragma unroll
        for (int c = 0; c < 4; c++) o[nt][c] = 0.f;

    for (int kt = 0; kt < NKT_ATT; kt++) {
        // wait K[kt] (V[kt] may still be in flight: in-flight groups are
        // {K[kt], V[kt]} at kt=0 or {V[kt], K... } — commit order keeps
        // wait1 precise: the older group is K[kt] at loop top.
        cp_wait1();
        __syncthreads();

        const unsigned* Qu = (const unsigned*)Qs;
        const unsigned* Pu = (const unsigned*)Ps;

        // ---- S = Q_tile(16) x K_tile(64)^T ----
        float s[8][4];
        #pragma unroll
        for (int nt = 0; nt < 8; nt++)
            #pragma unroll
            for (int c = 0; c < 4; c++) s[nt][c] = 0.f;

        #pragma unroll
        for (int kk = 0; kk < 128; kk += 8) {
            unsigned af[4];
            af[0] = Qu[(wrow + g) * QSTR + kk + t];
            af[1] = Qu[(wrow + 8 + g) * QSTR + kk + t];
            af[2] = Qu[(wrow + g) * QSTR + kk + 4 + t];
            af[3] = Qu[(wrow + 8 + g) * QSTR + kk + 4 + t];
            #pragma unroll
            for (int nt = 0; nt < 8; nt++) {
                unsigned bf[2];
                bf[0] = f2tf32(Ks[(nt * 8 + g) * KSTR + kk + t]);
                bf[1] = f2tf32(Ks[(nt * 8 + g) * KSTR + kk + 4 + t]);
                mma_tf32(s[nt], af, bf);
            }
        }

        // ---- online softmax ----
        float mx0 = -1e30f, mx1 = -1e30f;
        #pragma unroll
        for (int nt = 0; nt < 8; nt++) {
            mx0 = fmaxf(mx0, fmaxf(s[nt][0], s[nt][1]));
            mx1 = fmaxf(mx1, fmaxf(s[nt][2], s[nt][3]));
        }
        #pragma unroll
        for (int off = 1; off < 4; off <<= 1) {
            mx0 = fmaxf(mx0, __shfl_xor_sync(0xffffffffu, mx0, off));
            mx1 = fmaxf(mx1, __shfl_xor_sync(0xffffffffu, mx1, off));
        }
        float mn0 = fmaxf(m0, mx0), mn1 = fmaxf(m1, mx1);
        float c0 = __expf(m0 - mn0), c1 = __expf(m1 - mn1);
        m0 = mn0; m1 = mn1;

        float ls0 = 0.f, ls1 = 0.f;
        #pragma unroll
        for (int nt = 0; nt < 8; nt++) {
            float p00 = __expf(s[nt][0] - m0);
            float p01 = __expf(s[nt][1] - m0);
            float p10 = __expf(s[nt][2] - m1);
            float p11 = __expf(s[nt][3] - m1);
            ls0 += p00 + p01;          // unrounded sum (R10 order)
            ls1 += p10 + p11;
            uint2 pr0 = make_uint2(f2tf32(p00), f2tf32(p01));
            uint2 pr1 = make_uint2(f2tf32(p10), f2tf32(p11));
            *(uint2*)(Ps + g * PSTR + nt * 8 + 2 * t)       = pr0;
            *(uint2*)(Ps + (g + 8) * PSTR + nt * 8 + 2 * t) = pr1;
        }
        #pragma unroll
        for (int off = 1; off < 4; off <<= 1) {
            ls0 += __shfl_xor_sync(0xffffffffu, ls0, off);
            ls1 += __shfl_xor_sync(0xffffffffu, ls1, off);
        }
        l0 = l0 * c0 + ls0;
        l1 = l1 * c1 + ls1;
        #pragma unroll
        for (int nt = 0; nt < 16; nt++) {
            o[nt][0] *= c0; o[nt][1] *= c0;
            o[nt][2] *= c1; o[nt][3] *= c1;
        }

        // all warps done reading Ks -> prefetch K[kt+1] (overlaps PV)
        __syncthreads();
        if (kt + 1 < NKT_ATT) {
            ISSUE_K(kt + 1);
            cp_wait1();          // V[kt] done (older group); K[kt+1] in flight
        } else {
            cp_wait0();          // V[kt] done
        }
        __syncthreads();

        // ---- O += P(16x64) x V(64x128) ----
        #pragma unroll
        for (int kk = 0; kk < 64; kk += 8) {
            unsigned pf[4];
            pf[0] = Pu[g * PSTR + kk + t];
            pf[1] = Pu[(g + 8) * PSTR + kk + t];
            pf[2] = Pu[g * PSTR + kk + 4 + t];
            pf[3] = Pu[(g + 8) * PSTR + kk + 4 + t];
            #pragma unroll
            for (int nt = 0; nt < 16; nt++) {
                unsigned bf[2];
                bf[0] = f2tf32(Vs[(kk + t) * VSTR + nt * 8 + g]);
                bf[1] = f2tf32(Vs[(kk + 4 + t) * VSTR + nt * 8 + g]);
                mma_tf32(o[nt], pf, bf);
            }
        }

        // all warps done reading Vs -> prefetch V[kt+1] (overlaps next S)
        __syncthreads();
        if (kt + 1 < NKT_ATT)
            ISSUE_V(kt + 1);
    }
    #undef ISSUE_K
    #undef ISSUE_V

    // store AO pre-rounded to tf32 (O-proj consumes directly)
    float inv0 = 1.f / l0, inv1 = 1.f / l1;
    int r0 = q0 + wrow + g, r1 = q0 + wrow + 8 + g;
    #pragma unroll
    for (int nt = 0; nt < 16; nt++) {
        int d = nt * 8 + 2 * t;
        float2 v0 = make_float2(
            __uint_as_float(f2tf32(o[nt][0] * inv0)),
            __uint_as_float(f2tf32(o[nt][1] * inv0)));
        float2 v1 = make_float2(
            __uint_as_float(f2tf32(o[nt][2] * inv1)),
            __uint_as_float(f2tf32(o[nt][3] * inv1)));
        *(float2*)(Og + base + (size_t)r0 * HID + d) = v0;
        *(float2*)(Og + base + (size_t)r1 * HID + d) = v1;
    }
}

// =====================================================================
// launcher
// =====================================================================
extern "C" void kernel_launch(void* const* d_in, const int* in_sizes, int n_in,
                              void* d_out, int out_size)
{
    const float* X   = (const float*)d_in[0];
    const float* qw  = (const float*)d_in[1];
    const float* qb  = (const float*)d_in[2];
    const float* kw  = (const float*)d_in[3];
    const float* kb  = (const float*)d_in[4];
    const float* vw  = (const float*)d_in[5];
    const float* vb  = (const float*)d_in[6];
    const float* ow  = (const float*)d_in[7];
    const float* ob  = (const float*)d_in[8];
    const float* qg  = (const float*)d_in[9];
    const float* qnb = (const float*)d_in[10];
    const float* kg  = (const float*)d_in[11];
    const float* knb = (const float*)d_in[12];
    float* out = (float*)d_out;

    float *Q, *K, *V, *AO, *Xr, *Wr;
    cudaGetSymbolAddress((void**)&Q,  g_Q);
    cudaGetSymbolAddress((void**)&K,  g_K);
    cudaGetSymbolAddress((void**)&V,  g_V);
    cudaGetSymbolAddress((void**)&AO, g_AO);
    cudaGetSymbolAddress((void**)&Xr, g_Xr);
    cudaGetSymbolAddress((void**)&Wr, g_Wr);
    float* qwr = Wr;
    float* kwr = Wr + (size_t)HID * HID;
    float* vwr = Wr + 2 * (size_t)HID * HID;
    float* owr = Wr + 3 * (size_t)HID * HID;

    cudaFuncSetAttribute(flash_attn_tc,
                         cudaFuncAttributeMaxDynamicSharedMemorySize,
                         FLASH_SMEM);
    cudaFuncSetAttribute(qkv_gemm,
                         cudaFuncAttributeMaxDynamicSharedMemorySize,
                         GEMM_SMEM);
    cudaFuncSetAttribute(tf32_gemm_bias,
                         cudaFuncAttributeMaxDynamicSharedMemorySize,
                         GEMM_SMEM);

    // prep: round X and weights to exact tf32 once
    round_prep<<<dim3(1024, 5), 256>>>(X, qw, kw, vw, ow,
                                       Xr, qwr, kwr, vwr, owr);

    // fused QKV projection: one launch, z selects q/k/v
    dim3 gq(HID / 128, NTOK / 128, 3);   // (16, 32, 3)
    qkv_gemm<<<gq, 128, GEMM_SMEM>>>(Xr, qwr, kwr, vwr, qb, kb, vb, Q, K, V);

    qk_ln<<<NTOK, 512>>>(Q, K, qg, qnb, kg, knb);

    flash_attn_tc<<<dim3(2048 / 128, 32), 256, FLASH_SMEM>>>(Q, K, V, AO);

    dim3 gg(HID / 128, NTOK / 128);      // (16, 32)
    tf32_gemm_bias<<<gg, 128, GEMM_SMEM>>>(AO, owr, ob, out);
}

// round 15
// speedup vs baseline: 1.1712x; 1.0371x over previous
#include <cuda_runtime.h>
#include <cstdint>
#include <math.h>

#define HID 2048
#define NTOK 4096
#define HEADS 16
#define HDIM 128

// ---- scratch (static device arrays; no allocations allowed) ----
__device__ float g_Q[NTOK * HID];
__device__ float g_K[NTOK * HID];
__device__ float g_V[NTOK * HID];
__device__ float g_AO[NTOK * HID];
__device__ float g_Xr[NTOK * HID];        // tf32-rounded hidden_states
__device__ float g_Wr[4][HID * HID];      // tf32-rounded weights (same layout)

// =====================================================================
// helpers
// =====================================================================
__device__ __forceinline__ unsigned f2tf32(float f) {
    unsigned u;
    asm("cvt.rna.tf32.f32 %0, %1;" : "=r"(u) : "f"(f));
    return u;
}
__device__ __forceinline__ void mma_tf32(float* c, const unsigned* a,
                                         const unsigned* b) {
    asm volatile(
        "mma.sync.aligned.m16n8k8.row.col.f32.tf32.tf32.f32 "
        "{%0,%1,%2,%3}, {%4,%5,%6,%7}, {%8,%9}, {%0,%1,%2,%3};\n"
        : "+f"(c[0]), "+f"(c[1]), "+f"(c[2]), "+f"(c[3])
        : "r"(a[0]), "r"(a[1]), "r"(a[2]), "r"(a[3]),
          "r"(b[0]), "r"(b[1]));
}
__device__ __forceinline__ void cp16(void* smem_dst, const void* g) {
    unsigned saddr = (unsigned)__cvta_generic_to_shared(smem_dst);
    asm volatile("cp.async.cg.shared.global [%0], [%1], 16;\n"
                 :: "r"(saddr), "l"(g));
}
__device__ __forceinline__ void cp_commit() {
    asm volatile("cp.async.commit_group;\n");
}
__device__ __forceinline__ void cp_wait1() {
    asm volatile("cp.async.wait_group 1;\n");
}
__device__ __forceinline__ void cp_wait0() {
    asm volatile("cp.async.wait_group 0;\n");
}

// =====================================================================
// prep: round X and the 4 weights to exact tf32 values (rna), in gmem.
// =====================================================================
__global__ __launch_bounds__(256)
void round_prep(const float* __restrict__ X,
                const float* __restrict__ w0, const float* __restrict__ w1,
                const float* __restrict__ w2, const float* __restrict__ w3,
                float* __restrict__ Xr,
                float* __restrict__ r0, float* __restrict__ r1,
                float* __restrict__ r2, float* __restrict__ r3)
{
    int z = blockIdx.y;
    const float4* src;
    float4* dst;
    int n4;
    if (z == 0)      { src = (const float4*)X;  dst = (float4*)Xr; n4 = NTOK * HID / 4; }
    else if (z == 1) { src = (const float4*)w0; dst = (float4*)r0; n4 = HID * HID / 4; }
    else if (z == 2) { src = (const float4*)w1; dst = (float4*)r1; n4 = HID * HID / 4; }
    else if (z == 3) { src = (const float4*)w2; dst = (float4*)r2; n4 = HID * HID / 4; }
    else             { src = (const float4*)w3; dst = (float4*)r3; n4 = HID * HID / 4; }

    int i = blockIdx.x * blockDim.x + threadIdx.x;
    int stride = gridDim.x * blockDim.x;
    for (; i < n4; i += stride) {
        float4 v = src[i];
        v.x = __uint_as_float(f2tf32(v.x));
        v.y = __uint_as_float(f2tf32(v.y));
        v.z = __uint_as_float(f2tf32(v.z));
        v.w = __uint_as_float(f2tf32(v.w));
        dst[i] = v;
    }
}

// =====================================================================
// TF32 tensor-core GEMM with bias (pre-rounded inputs, no mainloop cvt)
// 128x128x32 block tile, 128 threads (4 warps, 2x2), warp tile 64x64.
// round_out: store C pre-rounded to tf32 (for V, consumed only by MMA).
// =====================================================================
#define ASTR 36
#define BSTR 136
#define GEMM_SMEM ((2 * 128 * ASTR + 2 * 32 * BSTR) * 4)   // 71680 B

__device__ __forceinline__
void gemm_body(const float* __restrict__ A, const float* __restrict__ B,
               const float* __restrict__ bias, float* __restrict__ C,
               int round_out)
{
    extern __shared__ float gsm[];
    float* Asm[2] = { gsm, gsm + 128 * ASTR };
    float* Bsm[2] = { gsm + 2 * 128 * ASTR, gsm + 2 * 128 * ASTR + 32 * BSTR };

    const int tid  = threadIdx.x;
    const int lane = tid & 31;
    const int g    = lane >> 2;
    const int t    = lane & 3;
    const int wid  = tid >> 5;
    const int warpM = wid & 1;
    const int warpN = wid >> 1;
    const int row0 = blockIdx.y * 128;
    const int col0 = blockIdx.x * 128;

    float acc[4][8][4];
    #pragma unroll
    for (int i = 0; i < 4; i++)
        #pragma unroll
        for (int j = 0; j < 8; j++)
            #pragma unroll
            for (int c = 0; c < 4; c++) acc[i][j][c] = 0.f;

    const int nk = HID >> 5;

    #define LOAD_TILE(bufi, kt_) { \
        const float* ag = A + (size_t)row0 * HID + (kt_) * 32; \
        _Pragma("unroll") \
        for (int j = 0; j < 8; j++) { \
            int idx = j * 128 + tid; \
            int r = idx >> 3, c = (idx & 7) * 4; \
            cp16(&Asm[bufi][r * ASTR + c], ag + (size_t)r * HID + c); \
        } \
        const float* bg = B + (size_t)((kt_) * 32) * HID + col0; \
        _Pragma("unroll") \
        for (int j = 0; j < 8; j++) { \
            int idx = j * 128 + tid; \
            int kr = idx >> 5, n = (idx & 31) * 4; \
            cp16(&Bsm[bufi][kr * BSTR + n], bg + (size_t)kr * HID + n); \
        } \
        cp_commit(); }

    LOAD_TILE(0, 0);

    int buf = 0;
    for (int kt = 0; kt < nk; kt++) {
        if (kt + 1 < nk) {
            LOAD_TILE(buf ^ 1, kt + 1);
            cp_wait1();
        } else {
            cp_wait0();
        }
        __syncthreads();

        const unsigned* as = (const unsigned*)Asm[buf];
        const unsigned* bs = (const unsigned*)Bsm[buf];

        #pragma unroll
        for (int kk = 0; kk < 32; kk += 8) {
            unsigned bf[8][2];
            #pragma unroll
            for (int tn = 0; tn < 8; tn++) {
                int n = warpN * 64 + tn * 8 + g;
                bf[tn][0] = bs[(kk +     t) * BSTR + n];
                bf[tn][1] = bs[(kk + 4 + t) * BSTR + n];
            }
            unsigned af[4][4];
            #pragma unroll
            for (int tm = 0; tm < 4; tm++) {
                int m = warpM * 64 + tm * 16 + g;
                af[tm][0] = as[m * ASTR + kk + t];
                af[tm][1] = as[(m + 8) * ASTR + kk + t];
                af[tm][2] = as[m * ASTR + kk + 4 + t];
                af[tm][3] = as[(m + 8) * ASTR + kk + 4 + t];
            }
            #pragma unroll
            for (int tm = 0; tm < 4; tm++)
                #pragma unroll
                for (int tn = 0; tn < 8; tn++)
                    mma_tf32(acc[tm][tn], af[tm], bf[tn]);
        }
        __syncthreads();
        buf ^= 1;
    }
    #undef LOAD_TILE

    #pragma unroll
    for (int tm = 0; tm < 4; tm++) {
        int mrow = row0 + warpM * 64 + tm * 16 + g;
        #pragma unroll
        for (int tn = 0; tn < 8; tn++) {
            int ncol = col0 + warpN * 64 + tn * 8 + t * 2;
            float b0 = bias[ncol], b1 = bias[ncol + 1];
            float2 v0 = make_float2(acc[tm][tn][0] + b0, acc[tm][tn][1] + b1);
            float2 v1 = make_float2(acc[tm][tn][2] + b0, acc[tm][tn][3] + b1);
            if (round_out) {
                v0.x = __uint_as_float(f2tf32(v0.x));
                v0.y = __uint_as_float(f2tf32(v0.y));
                v1.x = __uint_as_float(f2tf32(v1.x));
                v1.y = __uint_as_float(f2tf32(v1.y));
            }
            *(float2*)(C + (size_t)mrow * HID + ncol) = v0;
            *(float2*)(C + (size_t)(mrow + 8) * HID + ncol) = v1;
        }
    }
}

__global__ __launch_bounds__(128)
void qkv_gemm(const float* __restrict__ A,
              const float* __restrict__ W0, const float* __restrict__ W1,
              const float* __restrict__ W2,
              const float* __restrict__ b0, const float* __restrict__ b1,
              const float* __restrict__ b2,
              float* __restrict__ C0, float* __restrict__ C1,
              float* __restrict__ C2)
{
    const float* W = (blockIdx.z == 0) ? W0 : (blockIdx.z == 1) ? W1 : W2;
    const float* b = (blockIdx.z == 0) ? b0 : (blockIdx.z == 1) ? b1 : b2;
    float*       C = (blockIdx.z == 0) ? C0 : (blockIdx.z == 1) ? C1 : C2;
    // V (z==2) is consumed only by flash's MMA -> store pre-rounded tf32
    gemm_body(A, W, b, C, blockIdx.z == 2 ? 1 : 0);
}

__global__ __launch_bounds__(128)
void tf32_gemm_bias(const float* __restrict__ A, const float* __restrict__ B,
                    const float* __restrict__ bias, float* __restrict__ C)
{
    gemm_body(A, B, bias, C, 0);   // final output: never rounded
}

// =====================================================================
// Per-head LayerNorm over head_dim=128 for Q and K (in place).
// K output stored pre-rounded to tf32 (consumed only by flash's MMA,
// which previously applied the identical cvt.rna -> bit-identical).
// Q left raw (flash scales then rounds; pre-rounding would double-round).
// =====================================================================
__device__ __forceinline__ void ln_head(float* p, const float* g,
                                        const float* be, int lane,
                                        int round_out)
{
    float4 x = *(float4*)(p + lane * 4);
    float s  = x.x + x.y + x.z + x.w;
    float ss = x.x * x.x + x.y * x.y + x.z * x.z + x.w * x.w;
    #pragma unroll
    for (int off = 16; off > 0; off >>= 1) {
        s  += __shfl_xor_sync(0xffffffffu, s,  off);
        ss += __shfl_xor_sync(0xffffffffu, ss, off);
    }
    float mean = s * (1.f / 128.f);
    float var  = ss * (1.f / 128.f) - mean * mean;
    float rstd = rsqrtf(var + 1e-6f);
    float4 gg = *(const float4*)(g  + lane * 4);
    float4 bb = *(const float4*)(be + lane * 4);
    x.x = (x.x - mean) * rstd * gg.x + bb.x;
    x.y = (x.y - mean) * rstd * gg.y + bb.y;
    x.z = (x.z - mean) * rstd * gg.z + bb.z;
    x.w = (x.w - mean) * rstd * gg.w + bb.w;
    if (round_out) {
        x.x = __uint_as_float(f2tf32(x.x));
        x.y = __uint_as_float(f2tf32(x.y));
        x.z = __uint_as_float(f2tf32(x.z));
        x.w = __uint_as_float(f2tf32(x.w));
    }
    *(float4*)(p + lane * 4) = x;
}

__global__ __launch_bounds__(512)
void qk_ln(float* __restrict__ Q, float* __restrict__ K,
           const float* __restrict__ qg, const float* __restrict__ qb,
           const float* __restrict__ kg, const float* __restrict__ kb)
{
    int tk = blockIdx.x;
    int h = threadIdx.x >> 5;
    int lane = threadIdx.x & 31;
    ln_head(Q + (size_t)tk * HID + h * HDIM, qg, qb, lane, 0);
    ln_head(K + (size_t)tk * HID + h * HDIM, kg, kb, lane, 1);
}

// =====================================================================
// Tensor-core flash attention — cp.async split K/V pipeline (R14) with
// bare-LDS inner loops: K/V are pre-rounded by their producers, so no
// cvt in the mainloop. Q/P stored pre-rounded in smem as before.
// =====================================================================
#define QSTR 132
#define KSTR 132
#define VSTR 136
#define PSTR 68
#define FLASH_SMEM ((128 * QSTR + 64 * KSTR + 64 * VSTR + 8 * 16 * PSTR) * 4)
#define NKT_ATT (2048 / 64)

__global__ __launch_bounds__(256)
void flash_attn_tc(const float* __restrict__ Qg, const float* __restrict__ Kg,
                   const float* __restrict__ Vg, float* __restrict__ Og)
{
    extern __shared__ float sm[];
    float* Qs = sm;                       // 128 x QSTR (pre-rounded tf32 bits)
    float* Ks = Qs + 128 * QSTR;          // 64 x KSTR  (pre-rounded by qk_ln)
    float* Vs = Ks + 64 * KSTR;           // 64 x VSTR  (pre-rounded by qkv_gemm)
    float* Pw = Vs + 64 * VSTR;           // 8 x 16 x PSTR (pre-rounded)

    const int tid  = threadIdx.x;
    const int lane = tid & 31;
    const int w    = tid >> 5;
    const int g    = lane >> 2;
    const int t    = lane & 3;
    const int bh = blockIdx.y;
    const int b  = bh >> 4, h = bh & 15;
    const int q0 = blockIdx.x * 128;
    const size_t base = (size_t)b * 2048 * HID + (size_t)h * HDIM;
    const float scale = 0.08838834764831845f;

    float* Ps = Pw + w * 16 * PSTR;
    const int wrow = w * 16;

    #define ISSUE_K(kt_) { \
        const float* src = Kg + base + (size_t)((kt_) * 64) * HID; \
        _Pragma("unroll") \
        for (int j = 0; j < 8; j++) { \
            int i = j * 256 + tid; \
            int r = i >> 5, c4 = (i & 31) << 2; \
            cp16(Ks + r * KSTR + c4, src + (size_t)r * HID + c4); \
        } \
        cp_commit(); }
    #define ISSUE_V(kt_) { \
        const float* src = Vg + base + (size_t)((kt_) * 64) * HID; \
        _Pragma("unroll") \
        for (int j = 0; j < 8; j++) { \
            int i = j * 256 + tid; \
            int r = i >> 5, c4 = (i & 31) << 2; \
            cp16(Vs + r * VSTR + c4, src + (size_t)r * HID + c4); \
        } \
        cp_commit(); }

    // prologue: K0, V0 in flight; Q load overlaps them
    ISSUE_K(0);
    ISSUE_V(0);
    for (int i = tid; i < 128 * 32; i += 256) {
        int r = i >> 5, c4 = (i & 31) << 2;
        float4 q = *(const float4*)(Qg + base + (size_t)(q0 + r) * HID + c4);
        uint4 qu;
        qu.x = f2tf32(q.x * scale);
        qu.y = f2tf32(q.y * scale);
        qu.z = f2tf32(q.z * scale);
        qu.w = f2tf32(q.w * scale);
        *(uint4*)(Qs + r * QSTR + c4) = qu;
    }

    float m0 = -1e30f, m1 = -1e30f, l0 = 0.f, l1 = 0.f;
    float o[16][4];
    #pragma unroll
    for (int nt = 0; nt < 16; nt++)
        #pragma unroll
        for (int c = 0; c < 4; c++) o[nt][c] = 0.f;

    for (int kt = 0; kt < NKT_ATT; kt++) {
        cp_wait1();                       // K[kt] complete
        __syncthreads();

        const unsigned* Qu = (const unsigned*)Qs;
        const unsigned* Ku = (const unsigned*)Ks;
        const unsigned* Vu = (const unsigned*)Vs;
        const unsigned* Pu = (const unsigned*)Ps;

        // ---- S = Q_tile(16) x K_tile(64)^T ----
        float s[8][4];
        #pragma unroll
        for (int nt = 0; nt < 8; nt++)
            #pragma unroll
            for (int c = 0; c < 4; c++) s[nt][c] = 0.f;

        #pragma unroll
        for (int kk = 0; kk < 128; kk += 8) {
            unsigned af[4];
            af[0] = Qu[(wrow + g) * QSTR + kk + t];
            af[1] = Qu[(wrow + 8 + g) * QSTR + kk + t];
            af[2] = Qu[(wrow + g) * QSTR + kk + 4 + t];
            af[3] = Qu[(wrow + 8 + g) * QSTR + kk + 4 + t];
            #pragma unroll
            for (int nt = 0; nt < 8; nt++) {
                unsigned bf[2];
                bf[0] = Ku[(nt * 8 + g) * KSTR + kk + t];
                bf[1] = Ku[(nt * 8 + g) * KSTR + kk + 4 + t];
                mma_tf32(s[nt], af, bf);
            }
        }

        // ---- online softmax ----
        float mx0 = -1e30f, mx1 = -1e30f;
        #pragma unroll
        for (int nt = 0; nt < 8; nt++) {
            mx0 = fmaxf(mx0, fmaxf(s[nt][0], s[nt][1]));
            mx1 = fmaxf(mx1, fmaxf(s[nt][2], s[nt][3]));
        }
        #pragma unroll
        for (int off = 1; off < 4; off <<= 1) {
            mx0 = fmaxf(mx0, __shfl_xor_sync(0xffffffffu, mx0, off));
            mx1 = fmaxf(mx1, __shfl_xor_sync(0xffffffffu, mx1, off));
        }
        float mn0 = fmaxf(m0, mx0), mn1 = fmaxf(m1, mx1);
        float c0 = __expf(m0 - mn0), c1 = __expf(m1 - mn1);
        m0 = mn0; m1 = mn1;

        float ls0 = 0.f, ls1 = 0.f;
        #pragma unroll
        for (int nt = 0; nt < 8; nt++) {
            float p00 = __expf(s[nt][0] - m0);
            float p01 = __expf(s[nt][1] - m0);
            float p10 = __expf(s[nt][2] - m1);
            float p11 = __expf(s[nt][3] - m1);
            ls0 += p00 + p01;          // unrounded sum (R10 order)
            ls1 += p10 + p11;
            uint2 pr0 = make_uint2(f2tf32(p00), f2tf32(p01));
            uint2 pr1 = make_uint2(f2tf32(p10), f2tf32(p11));
            *(uint2*)(Ps + g * PSTR + nt * 8 + 2 * t)       = pr0;
            *(uint2*)(Ps + (g + 8) * PSTR + nt * 8 + 2 * t) = pr1;
        }
        #pragma unroll
        for (int off = 1; off < 4; off <<= 1) {
            ls0 += __shfl_xor_sync(0xffffffffu, ls0, off);
            ls1 += __shfl_xor_sync(0xffffffffu, ls1, off);
        }
        l0 = l0 * c0 + ls0;
        l1 = l1 * c1 + ls1;
        #pragma unroll
        for (int nt = 0; nt < 16; nt++) {
            o[nt][0] *= c0; o[nt][1] *= c0;
            o[nt][2] *= c1; o[nt][3] *= c1;
        }

        // all warps done reading Ks -> prefetch K[kt+1] (overlaps PV)
        __syncthreads();
        if (kt + 1 < NKT_ATT) {
            ISSUE_K(kt + 1);
            cp_wait1();          // V[kt] done (older group); K[kt+1] in flight
        } else {
            cp_wait0();          // V[kt] done
        }
        __syncthreads();

        // ---- O += P(16x64) x V(64x128) ----
        #pragma unroll
        for (int kk = 0; kk < 64; kk += 8) {
            unsigned pf[4];
            pf[0] = Pu[g * PSTR + kk + t];
            pf[1] = Pu[(g + 8) * PSTR + kk + t];
            pf[2] = Pu[g * PSTR + kk + 4 + t];
            pf[3] = Pu[(g + 8) * PSTR + kk + 4 + t];
            #pragma unroll
            for (int nt = 0; nt < 16; nt++) {
                unsigned bf[2];
                bf[0] = Vu[(kk + t) * VSTR + nt * 8 + g];
                bf[1] = Vu[(kk + 4 + t) * VSTR + nt * 8 + g];
                mma_tf32(o[nt], pf, bf);
            }
        }

        // all warps done reading Vs -> prefetch V[kt+1] (overlaps next S)
        __syncthreads();
        if (kt + 1 < NKT_ATT)
            ISSUE_V(kt + 1);
    }
    #undef ISSUE_K
    #undef ISSUE_V

    // store AO pre-rounded to tf32 (O-proj consumes directly)
    float inv0 = 1.f / l0, inv1 = 1.f / l1;
    int r0 = q0 + wrow + g, r1 = q0 + wrow + 8 + g;
    #pragma unroll
    for (int nt = 0; nt < 16; nt++) {
        int d = nt * 8 + 2 * t;
        float2 v0 = make_float2(
            __uint_as_float(f2tf32(o[nt][0] * inv0)),
            __uint_as_float(f2tf32(o[nt][1] * inv0)));
        float2 v1 = make_float2(
            __uint_as_float(f2tf32(o[nt][2] * inv1)),
            __uint_as_float(f2tf32(o[nt][3] * inv1)));
        *(float2*)(Og + base + (size_t)r0 * HID + d) = v0;
        *(float2*)(Og + base + (size_t)r1 * HID + d) = v1;
    }
}

// =====================================================================
// launcher
// =====================================================================
extern "C" void kernel_launch(void* const* d_in, const int* in_sizes, int n_in,
                              void* d_out, int out_size)
{
    const float* X   = (const float*)d_in[0];
    const float* qw  = (const float*)d_in[1];
    const float* qb  = (const float*)d_in[2];
    const float* kw  = (const float*)d_in[3];
    const float* kb  = (const float*)d_in[4];
    const float* vw  = (const float*)d_in[5];
    const float* vb  = (const float*)d_in[6];
    const float* ow  = (const float*)d_in[7];
    const float* ob  = (const float*)d_in[8];
    const float* qg  = (const float*)d_in[9];
    const float* qnb = (const float*)d_in[10];
    const float* kg  = (const float*)d_in[11];
    const float* knb = (const float*)d_in[12];
    float* out = (float*)d_out;

    float *Q, *K, *V, *AO, *Xr, *Wr;
    cudaGetSymbolAddress((void**)&Q,  g_Q);
    cudaGetSymbolAddress((void**)&K,  g_K);
    cudaGetSymbolAddress((void**)&V,  g_V);
    cudaGetSymbolAddress((void**)&AO, g_AO);
    cudaGetSymbolAddress((void**)&Xr, g_Xr);
    cudaGetSymbolAddress((void**)&Wr, g_Wr);
    float* qwr = Wr;
    float* kwr = Wr + (size_t)HID * HID;
    float* vwr = Wr + 2 * (size_t)HID * HID;
    float* owr = Wr + 3 * (size_t)HID * HID;

    cudaFuncSetAttribute(flash_attn_tc,
                         cudaFuncAttributeMaxDynamicSharedMemorySize,
                         FLASH_SMEM);
    cudaFuncSetAttribute(qkv_gemm,
                         cudaFuncAttributeMaxDynamicSharedMemorySize,
                         GEMM_SMEM);
    cudaFuncSetAttribute(tf32_gemm_bias,
                         cudaFuncAttributeMaxDynamicSharedMemorySize,
                         GEMM_SMEM);

    // prep: round X and weights to exact tf32 once
    round_prep<<<dim3(1024, 5), 256>>>(X, qw, kw, vw, ow,
                                       Xr, qwr, kwr, vwr, owr);

    // fused QKV projection: one launch, z selects q/k/v (V pre-rounded)
    dim3 gq(HID / 128, NTOK / 128, 3);   // (16, 32, 3)
    qkv_gemm<<<gq, 128, GEMM_SMEM>>>(Xr, qwr, kwr, vwr, qb, kb, vb, Q, K, V);

    qk_ln<<<NTOK, 512>>>(Q, K, qg, qnb, kg, knb);

    flash_attn_tc<<<dim3(2048 / 128, 32), 256, FLASH_SMEM>>>(Q, K, V, AO);

    dim3 gg(HID / 128, NTOK / 128);      // (16, 32)
    tf32_gemm_bias<<<gg, 128, GEMM_SMEM>>>(AO, owr, ob, out);
}